// round 13
// baseline (speedup 1.0000x reference)
#include <cuda_runtime.h>
#include <cuda_fp16.h>
#include <cstdint>

// Problem constants
#define NBM   64      // B*M
#define LSEQ  512
#define CDIM  512
#define NH    8
#define HD    64
#define NROWS (NBM*LSEQ)   // 32768

// All scratch stored as uint = half2 pairs, pair-index perm16'd within
// 16-pair (64B) groups. One LDS.128 then yields operand fragments for TWO
// m16n8k16 k-steps: {pair t, t+4, 8+t, 12+t}.
__device__ __align__(16) unsigned g_xt[NROWS*CDIM/2];     // [row][256 k-pairs]
__device__ __align__(16) unsigned g_q [NBM*NH*LSEQ*HD/2]; // [bm][h][l][32 d-pairs], pre-scaled
__device__ __align__(16) unsigned g_k [NBM*NH*LSEQ*HD/2]; // [bm][h][l][32 d-pairs]
__device__ __align__(16) unsigned g_v [NBM*NH*HD*LSEQ/2]; // [bm][h][d][256 l-pairs] (V^T)
__device__ __align__(16) unsigned g_wt[3*CDIM*CDIM/2];    // [mat][n][256 k-pairs]

// perm16 on pair index p (0..15): pos = 4*(p&3) + ((p>>2)&1) + 2*((p>>3)&1)
__device__ __forceinline__ int p16(int v) {
    return 4 * (v & 3) + ((v >> 2) & 1) + 2 * ((v >> 3) & 1);
}

__device__ __forceinline__ unsigned pack2(float a, float b) {
    __half2 h = __floats2half2_rn(a, b);
    return *reinterpret_cast<unsigned*>(&h);
}

__device__ __forceinline__ float ex2(float x) {
    float r;
    asm("ex2.approx.ftz.f32 %0, %1;" : "=f"(r) : "f"(x));
    return r;
}

__device__ __forceinline__ void mma_f16(float* c, const unsigned* a, const unsigned* b) {
    asm("mma.sync.aligned.m16n8k16.row.col.f32.f16.f16.f32 "
        "{%0,%1,%2,%3}, {%4,%5,%6,%7}, {%8,%9}, {%0,%1,%2,%3};"
        : "+f"(c[0]), "+f"(c[1]), "+f"(c[2]), "+f"(c[3])
        : "r"(a[0]), "r"(a[1]), "r"(a[2]), "r"(a[3]),
          "r"(b[0]), "r"(b[1]));
}

__device__ __forceinline__ uint32_t smem_u32(const void* p) {
    uint32_t a;
    asm("{ .reg .u64 t; cvta.to.shared.u64 t, %1; cvt.u32.u64 %0, t; }" : "=r"(a) : "l"(p));
    return a;
}

#define CP16(dst, src) \
    asm volatile("cp.async.cg.shared.global [%0], [%1], 16;" :: "r"(dst), "l"(src) : "memory")
#define CP_COMMIT() asm volatile("cp.async.commit_group;" ::: "memory")
#define CP_WAIT(n)  asm volatile("cp.async.wait_group %0;" :: "n"(n) : "memory")

// ---------------------------------------------------------------------------
// Pre-pass A: g_xt = fp16(x) pairs, pair-perm'd.
// ---------------------------------------------------------------------------
__global__ __launch_bounds__(256) void xt_kernel(const float* __restrict__ x)
{
    int p = blockIdx.x * 256 + threadIdx.x;        // global pair index
    float2 v = ((const float2*)x)[p];
    g_xt[(p & ~15) | p16(p & 15)] = pack2(v.x, v.y);
}

// ---------------------------------------------------------------------------
// Pre-pass B: g_wt[mat][n][k-pairs] = fp16(W^T), pair-perm'd.
// ---------------------------------------------------------------------------
__global__ __launch_bounds__(256) void wt_kernel(
    const float* __restrict__ Wq, const float* __restrict__ Wk,
    const float* __restrict__ Wv)
{
    __shared__ float s[32][33];
    const float* W = (blockIdx.z == 0) ? Wq : (blockIdx.z == 1) ? Wk : Wv;
    const int k0 = blockIdx.x * 32, n0 = blockIdx.y * 32;
    const int tid = threadIdx.x;
    {
        int kl = tid >> 3, n4 = tid & 7;
        float4 v = *(const float4*)&W[(size_t)(k0 + kl) * CDIM + n0 + n4 * 4];
        s[kl][n4 * 4 + 0] = v.x; s[kl][n4 * 4 + 1] = v.y;
        s[kl][n4 * 4 + 2] = v.z; s[kl][n4 * 4 + 3] = v.w;
    }
    __syncthreads();
    {
        int nl = tid >> 3, k4 = tid & 7;
        unsigned uA = pack2(s[k4 * 4 + 0][nl], s[k4 * 4 + 1][nl]);
        unsigned uB = pack2(s[k4 * 4 + 2][nl], s[k4 * 4 + 3][nl]);
        size_t base = (size_t)(blockIdx.z * CDIM + n0 + nl) * 256;
        int pA = (k0 >> 1) + k4 * 2, pB = pA + 1;
        g_wt[base + ((pA & ~15) | p16(pA & 15))] = uA;
        g_wt[base + ((pB & ~15) | p16(pB & 15))] = uB;
    }
}

// ---------------------------------------------------------------------------
// Kernel 1: QKV projection, fp16 m16n8k16. CTA 128x128, 8 warps (2m x 4n).
// K=512 in 8 pair-stages (64 elems = 2 conflict-free 16-pair half-tiles),
// ring-3 slots, fully unrolled, 2 CTAs/SM.
// ---------------------------------------------------------------------------
#define QKV_HTILE 2048                   // uints: one 128x16-pair operand tile
#define QKV_PAIRS 8192                   // uints per slot: A0,B0,A1,B1
#define QKV_SMEMB (3*QKV_PAIRS*4)        // 98304 bytes

__global__ __launch_bounds__(256, 2) void qkv_f16(
    const float* __restrict__ bq, const float* __restrict__ bk,
    const float* __restrict__ bv)
{
    extern __shared__ unsigned smem[];
    const uint32_t sbase = smem_u32(smem);

    const int tid  = threadIdx.x;
    const int lane = tid & 31;
    const int warp = tid >> 5;
    const int g    = lane >> 2;
    const int t    = lane & 3;
    const int wm   = (warp >> 2) * 64;
    const int wn   = (warp & 3) * 32;

    const int gx = blockIdx.x;           // 0..11
    const int gy = blockIdx.y;           // 0..255
    const bool isV = gx >= 8;
    const int mat  = isV ? 2 : (gx >> 2);
    const int col0 = isV ? 0 : (gx & 3) * 128;
    const int d0   = isV ? (gx - 8) * 128 : 0;
    const int r0   = gy * 128;

    const unsigned* Asrc;
    const unsigned* Bsrc;
    if (!isV) {
        Asrc = g_xt + (size_t)r0 * 256;
        Bsrc = g_wt + (size_t)(mat * CDIM + col0) * 256;
    } else {
        Asrc = g_wt + (size_t)(2 * CDIM + d0) * 256;
        Bsrc = g_xt + (size_t)r0 * 256;
    }
    const float* bias = (mat == 0) ? bq : (mat == 1) ? bk : bv;

    // staging: 8 CP16/thread/pair-stage
    const int srow = tid >> 1;           // 0..127
    const int sc   = tid & 1;
    const unsigned* aS = Asrc + (size_t)srow * 256 + sc * 8;
    const unsigned* bS = Bsrc + (size_t)srow * 256 + sc * 8;
    const uint32_t sOff = (uint32_t)(srow * 16 + sc * 8) * 4;

    auto stage_pair = [&](int p, int slot) {
        uint32_t base = sbase + (uint32_t)slot * (QKV_PAIRS * 4) + sOff;
        const unsigned* sa = aS + p * 32;
        const unsigned* sb = bS + p * 32;
        CP16(base,                      sa);      CP16(base + 16,                      sa + 4);
        CP16(base + QKV_HTILE * 4,      sb);      CP16(base + QKV_HTILE * 4 + 16,      sb + 4);
        CP16(base + 2 * QKV_HTILE * 4,  sa + 16); CP16(base + 2 * QKV_HTILE * 4 + 16,  sa + 20);
        CP16(base + 3 * QKV_HTILE * 4,  sb + 16); CP16(base + 3 * QKV_HTILE * 4 + 16,  sb + 20);
        CP_COMMIT();
    };

    float acc[4][4][4];
    #pragma unroll
    for (int mi = 0; mi < 4; mi++)
        #pragma unroll
        for (int ni = 0; ni < 4; ni++)
            #pragma unroll
            for (int e = 0; e < 4; e++) acc[mi][ni][e] = 0.f;

    auto compute_tile = [&](const unsigned* As) {
        const unsigned* Bs = As + QKV_HTILE;
        unsigned a0[4][4], a1[4][4];
        #pragma unroll
        for (int mi = 0; mi < 4; mi++) {
            int rb = wm + mi * 16 + g;
            uint4 lo = *(const uint4*)&As[rb * 16 + 4 * t];
            uint4 hi = *(const uint4*)&As[(rb + 8) * 16 + 4 * t];
            a0[mi][0] = lo.x; a0[mi][1] = hi.x; a0[mi][2] = lo.y; a0[mi][3] = hi.y;
            a1[mi][0] = lo.z; a1[mi][1] = hi.z; a1[mi][2] = lo.w; a1[mi][3] = hi.w;
        }
        #pragma unroll
        for (int ni = 0; ni < 4; ni++) {
            uint4 u = *(const uint4*)&Bs[(wn + ni * 8 + g) * 16 + 4 * t];
            unsigned b0[2] = { u.x, u.y }, b1[2] = { u.z, u.w };
            #pragma unroll
            for (int mi = 0; mi < 4; mi++) {
                mma_f16(acc[mi][ni], a0[mi], b0);
                mma_f16(acc[mi][ni], a1[mi], b1);
            }
        }
    };

    stage_pair(0, 0); stage_pair(1, 1);

    #pragma unroll
    for (int p = 0; p < 8; p++) {
        CP_WAIT(1);
        __syncthreads();
        if (p < 6) stage_pair(p + 2, (p + 2) % 3);
        else       CP_COMMIT();
        const unsigned* base = smem + (p % 3) * QKV_PAIRS;
        compute_tile(base);
        compute_tile(base + 2 * QKV_HTILE);
    }
    __syncthreads();

    // Epilogue
    const float kInv = 1.4426950408889634f * 0.125f;  // log2(e)/sqrt(64), folded into Q
    unsigned* qk = (mat == 0) ? g_q : g_k;

    #pragma unroll
    for (int mi = 0; mi < 4; mi++) {
        #pragma unroll
        for (int ep = 0; ep < 2; ep++) {
            int rowD = wm + mi * 16 + g + ep * 8;
            #pragma unroll
            for (int ni = 0; ni < 4; ni++) {
                float v0 = acc[mi][ni][2 * ep];
                float v1 = acc[mi][ni][2 * ep + 1];
                if (!isV) {
                    int R = r0 + rowD;
                    int bm = R >> 9, l = R & 511;
                    int c = col0 + wn + ni * 8 + t * 2;
                    int h = c >> 6, d = c & 63;
                    v0 += bias[c]; v1 += bias[c + 1];
                    if (mat == 0) { v0 *= kInv; v1 *= kInv; }
                    int dp = d >> 1;
                    int pos = (dp & ~15) | p16(dp & 15);
                    qk[((size_t)(bm * NH + h) * LSEQ + l) * 32 + pos] = pack2(v0, v1);
                } else {
                    int dg = d0 + rowD;              // 0..511
                    int h = dg >> 6, d = dg & 63;
                    int lc = wn + ni * 8 + t * 2;
                    int L = r0 + lc;
                    int bm = L >> 9, ll = L & 511;
                    float bv_ = bias[dg];
                    v0 += bv_; v1 += bv_;
                    int lp = ll >> 1;
                    int pos = (lp & ~15) | p16(lp & 15);
                    g_v[((size_t)(bm * NH + h) * HD + d) * 256 + pos] = pack2(v0, v1);
                }
            }
        }
    }
}

// ---------------------------------------------------------------------------
// Kernel 2: flash attention, fp16 m16n8k16. CTA 128 q-rows (8 warps x 16),
// 64-key j-tiles double-buffered, 2 CTAs/SM. Q frags via LDG.
// O^T = V^T P^T with P fragments SELF-OWNED (zero shuffles).
// Softmax/O-mma interleaved by half (e) so MUFU overlaps tensor.
// ---------------------------------------------------------------------------
#define AST 48
#define KS_OFF(b) ((b) * 64 * AST)
#define VS_OFF(b) (2 * 64 * AST + (b) * 64 * AST)
#define ATTN_SMEMB (4 * 64 * AST * 4)    // 49152 bytes

__global__ __launch_bounds__(256, 2) void attn_kernel(float* __restrict__ out)
{
    extern __shared__ unsigned asmem[];
    const uint32_t sbase = smem_u32(asmem);

    const int l0 = blockIdx.x * 128;
    const int h  = blockIdx.y;
    const int bm = blockIdx.z;

    const int tid  = threadIdx.x;
    const int lane = tid & 31;
    const int warp = tid >> 5;
    const int g    = lane >> 2;
    const int t    = lane & 3;
    const int wr   = warp * 16;

    const unsigned* qb = g_q + (size_t)(bm * NH + h) * LSEQ * 32;
    const unsigned* kb = g_k + (size_t)(bm * NH + h) * LSEQ * 32;
    const unsigned* vb = g_v + (size_t)(bm * NH + h) * HD * 256;

    const int sr = tid >> 2, sch = tid & 3;

    // ---- stage K0 + V0 ----
    {
        uint32_t dK = sbase + (uint32_t)(KS_OFF(0) + sr * AST + sch * 8) * 4;
        const unsigned* sK = kb + (size_t)sr * 32 + sch * 8;
        CP16(dK, sK); CP16(dK + 16, sK + 4);
        uint32_t dV = sbase + (uint32_t)(VS_OFF(0) + sr * AST + sch * 8) * 4;
        const unsigned* sV = vb + (size_t)sr * 256 + sch * 8;
        CP16(dV, sV); CP16(dV + 16, sV + 4);
        CP_COMMIT();
    }

    // ---- Q fragments via LDG (Q pre-scaled by log2(e)/8) ----
    unsigned qa[4][4];
    {
        const unsigned* p0 = qb + (size_t)(l0 + wr + g) * 32 + 4 * t;
        const unsigned* p8 = qb + (size_t)(l0 + wr + g + 8) * 32 + 4 * t;
        uint4 A0 = *(const uint4*)p0;
        uint4 A1 = *(const uint4*)(p0 + 16);
        uint4 B0 = *(const uint4*)p8;
        uint4 B1 = *(const uint4*)(p8 + 16);
        qa[0][0] = A0.x; qa[0][1] = B0.x; qa[0][2] = A0.y; qa[0][3] = B0.y;
        qa[1][0] = A0.z; qa[1][1] = B0.z; qa[1][2] = A0.w; qa[1][3] = B0.w;
        qa[2][0] = A1.x; qa[2][1] = B1.x; qa[2][2] = A1.y; qa[2][3] = B1.y;
        qa[3][0] = A1.z; qa[3][1] = B1.z; qa[3][2] = A1.w; qa[3][3] = B1.w;
    }

    float oacc[4][2][4];
    #pragma unroll
    for (int mi = 0; mi < 4; mi++)
        #pragma unroll
        for (int nq = 0; nq < 2; nq++)
            #pragma unroll
            for (int e = 0; e < 4; e++) oacc[mi][nq][e] = 0.f;

    float mrow[2] = { -3.0e38f, -3.0e38f };
    float lsum[2] = { 0.f, 0.f };

    CP_WAIT(0);
    __syncthreads();

    for (int j = 0; j < 8; j++) {
        const int b = j & 1;
        if (j < 7) {
            const int jn = (j + 1) * 64;
            uint32_t dK = sbase + (uint32_t)(KS_OFF(b ^ 1) + sr * AST + sch * 8) * 4;
            const unsigned* sK = kb + (size_t)(jn + sr) * 32 + sch * 8;
            CP16(dK, sK); CP16(dK + 16, sK + 4);
            uint32_t dV = sbase + (uint32_t)(VS_OFF(b ^ 1) + sr * AST + sch * 8) * 4;
            const unsigned* sV = vb + (size_t)sr * 256 + (jn >> 1) + sch * 8;
            CP16(dV, sV); CP16(dV + 16, sV + 4);
            CP_COMMIT();
        }

        const unsigned* Ks = asmem + KS_OFF(b);
        const unsigned* Vs = asmem + VS_OFF(b);

        // ---- S = Q K^T ----
        float sacc[8][4];
        #pragma unroll
        for (int ni = 0; ni < 8; ni++)
            #pragma unroll
            for (int e = 0; e < 4; e++) sacc[ni][e] = 0.f;

        #pragma unroll
        for (int ni = 0; ni < 8; ni++) {
            const unsigned* kr = Ks + (8 * ni + g) * AST + 4 * t;
            uint4 u0 = *(const uint4*)kr;
            uint4 u1 = *(const uint4*)(kr + 16);
            unsigned b0[2] = { u0.x, u0.y }, b1[2] = { u0.z, u0.w };
            unsigned b2[2] = { u1.x, u1.y }, b3[2] = { u1.z, u1.w };
            mma_f16(sacc[ni], qa[0], b0);
            mma_f16(sacc[ni], qa[1], b1);
            mma_f16(sacc[ni], qa[2], b2);
            mma_f16(sacc[ni], qa[3], b3);
        }

        // ---- per-half softmax + O-mma, interleaved (MUFU overlaps tensor) --
        #pragma unroll
        for (int e = 0; e < 2; e++) {
            // max tree over 16 values
            float v8[8];
            #pragma unroll
            for (int ni = 0; ni < 8; ni++)
                v8[ni] = fmaxf(sacc[ni][2 * e], sacc[ni][2 * e + 1]);
            v8[0] = fmaxf(v8[0], v8[4]); v8[1] = fmaxf(v8[1], v8[5]);
            v8[2] = fmaxf(v8[2], v8[6]); v8[3] = fmaxf(v8[3], v8[7]);
            v8[0] = fmaxf(v8[0], v8[2]); v8[1] = fmaxf(v8[1], v8[3]);
            float mt = fmaxf(v8[0], v8[1]);
            mt = fmaxf(mt, __shfl_xor_sync(0xffffffffu, mt, 1));
            mt = fmaxf(mt, __shfl_xor_sync(0xffffffffu, mt, 2));
            float mnew = fmaxf(mrow[e], mt);
            float al = ex2(mrow[e] - mnew);
            mrow[e] = mnew;

            unsigned ppl[8];
            float rs = 0.f;
            #pragma unroll
            for (int ni = 0; ni < 8; ni++) {
                float p0 = ex2(sacc[ni][2 * e]     - mnew);
                float p1 = ex2(sacc[ni][2 * e + 1] - mnew);
                rs += p0 + p1;
                ppl[ni] = pack2(p0, p1);
            }
            rs += __shfl_xor_sync(0xffffffffu, rs, 1);
            rs += __shfl_xor_sync(0xffffffffu, rs, 2);
            lsum[e] = lsum[e] * al + rs;

            // rescale this half's O^T columns
            float a0 = __shfl_sync(0xffffffffu, al, 8 * t);
            float a1 = __shfl_sync(0xffffffffu, al, 8 * t + 4);
            #pragma unroll
            for (int mi = 0; mi < 4; mi++) {
                oacc[mi][e][0] *= a0; oacc[mi][e][2] *= a0;
                oacc[mi][e][1] *= a1; oacc[mi][e][3] *= a1;
            }

            // O^T += V^T P^T for this half (P frags self-owned)
            unsigned bb0[2] = { ppl[0], ppl[1] };
            unsigned bb1[2] = { ppl[2], ppl[3] };
            unsigned bb2[2] = { ppl[4], ppl[5] };
            unsigned bb3[2] = { ppl[6], ppl[7] };
            #pragma unroll
            for (int mi = 0; mi < 4; mi++) {
                const unsigned* vr  = Vs + (16 * mi + g) * AST + 4 * t;
                const unsigned* vr8 = Vs + (16 * mi + g + 8) * AST + 4 * t;
                uint4 lo = *(const uint4*)vr;
                uint4 hi = *(const uint4*)vr8;
                unsigned a0v[4] = { lo.x, hi.x, lo.y, hi.y };
                unsigned a1v[4] = { lo.z, hi.z, lo.w, hi.w };
                mma_f16(oacc[mi][e], a0v, bb0);
                mma_f16(oacc[mi][e], a1v, bb1);
                uint4 lo2 = *(const uint4*)(vr + 16);
                uint4 hi2 = *(const uint4*)(vr8 + 16);
                unsigned a2v[4] = { lo2.x, hi2.x, lo2.y, hi2.y };
                unsigned a3v[4] = { lo2.z, hi2.z, lo2.w, hi2.w };
                mma_f16(oacc[mi][e], a2v, bb2);
                mma_f16(oacc[mi][e], a3v, bb3);
            }
        }

        if (j < 7) CP_WAIT(0);
        __syncthreads();
    }

    // ---- epilogue: per-row 1/lsum via shuffle, transposed STG ----
    #pragma unroll
    for (int nq = 0; nq < 2; nq++) {
        float L0 = __shfl_sync(0xffffffffu, lsum[nq], 8 * t);
        float L1 = __shfl_sync(0xffffffffu, lsum[nq], 8 * t + 4);
        float inv0 = 1.f / L0, inv1 = 1.f / L1;
        int q0 = l0 + wr + 8 * nq + 2 * t;
        float* o0 = out + ((size_t)bm * LSEQ + q0) * CDIM + h * HD;
        float* o1 = o0 + CDIM;
        #pragma unroll
        for (int mi = 0; mi < 4; mi++) {
            o0[mi * 16 + g]     = oacc[mi][nq][0] * inv0;
            o1[mi * 16 + g]     = oacc[mi][nq][1] * inv1;
            o0[mi * 16 + g + 8] = oacc[mi][nq][2] * inv0;
            o1[mi * 16 + g + 8] = oacc[mi][nq][3] * inv1;
        }
    }
}

extern "C" void kernel_launch(void* const* d_in, const int* in_sizes, int n_in,
                              void* d_out, int out_size)
{
    const float* x  = (const float*)d_in[0];
    const float* Wq = (const float*)d_in[1];
    const float* bq = (const float*)d_in[2];
    const float* Wk = (const float*)d_in[3];
    const float* bk = (const float*)d_in[4];
    const float* Wv = (const float*)d_in[5];
    const float* bv = (const float*)d_in[6];
    float* out = (float*)d_out;

    xt_kernel<<<NROWS * CDIM / 2 / 256, 256>>>(x);
    wt_kernel<<<dim3(16, 16, 3), 256>>>(Wq, Wk, Wv);

    cudaFuncSetAttribute(qkv_f16,
                         cudaFuncAttributeMaxDynamicSharedMemorySize, QKV_SMEMB);
    qkv_f16<<<dim3(12, 256), 256, QKV_SMEMB>>>(bq, bk, bv);

    cudaFuncSetAttribute(attn_kernel,
                         cudaFuncAttributeMaxDynamicSharedMemorySize, ATTN_SMEMB);
    attn_kernel<<<dim3(4, NH, NBM), 256, ATTN_SMEMB>>>(out);
}

// round 14
// speedup vs baseline: 1.0221x; 1.0221x over previous
#include <cuda_runtime.h>
#include <cuda_fp16.h>
#include <cstdint>

// Problem constants
#define NBM   64      // B*M
#define LSEQ  512
#define CDIM  512
#define NH    8
#define HD    64
#define NROWS (NBM*LSEQ)   // 32768

// All scratch stored as uint = half2 pairs, pair-index perm16'd within
// 16-pair (64B) groups. One LDS.128 then yields operand fragments for TWO
// m16n8k16 k-steps: {pair t, t+4, 8+t, 12+t}.
__device__ __align__(16) unsigned g_xt[NROWS*CDIM/2];     // [row][256 k-pairs]
__device__ __align__(16) unsigned g_q [NBM*NH*LSEQ*HD/2]; // [bm][h][l][32 d-pairs], pre-scaled
__device__ __align__(16) unsigned g_k [NBM*NH*LSEQ*HD/2]; // [bm][h][l][32 d-pairs]
__device__ __align__(16) unsigned g_v [NBM*NH*HD*LSEQ/2]; // [bm][h][d][256 l-pairs] (V^T)
__device__ __align__(16) unsigned g_wt[3*CDIM*CDIM/2];    // [mat][n][256 k-pairs]

// perm16 on pair index p (0..15): pos = 4*(p&3) + ((p>>2)&1) + 2*((p>>3)&1)
__device__ __forceinline__ int p16(int v) {
    return 4 * (v & 3) + ((v >> 2) & 1) + 2 * ((v >> 3) & 1);
}

__device__ __forceinline__ unsigned pack2(float a, float b) {
    __half2 h = __floats2half2_rn(a, b);
    return *reinterpret_cast<unsigned*>(&h);
}

__device__ __forceinline__ float ex2(float x) {
    float r;
    asm("ex2.approx.ftz.f32 %0, %1;" : "=f"(r) : "f"(x));
    return r;
}

__device__ __forceinline__ unsigned ex2_h2(unsigned x) {
    unsigned r;
    asm("ex2.approx.f16x2 %0, %1;" : "=r"(r) : "r"(x));
    return r;
}

__device__ __forceinline__ void mma_f16(float* c, const unsigned* a, const unsigned* b) {
    asm("mma.sync.aligned.m16n8k16.row.col.f32.f16.f16.f32 "
        "{%0,%1,%2,%3}, {%4,%5,%6,%7}, {%8,%9}, {%0,%1,%2,%3};"
        : "+f"(c[0]), "+f"(c[1]), "+f"(c[2]), "+f"(c[3])
        : "r"(a[0]), "r"(a[1]), "r"(a[2]), "r"(a[3]),
          "r"(b[0]), "r"(b[1]));
}

__device__ __forceinline__ uint32_t smem_u32(const void* p) {
    uint32_t a;
    asm("{ .reg .u64 t; cvta.to.shared.u64 t, %1; cvt.u32.u64 %0, t; }" : "=r"(a) : "l"(p));
    return a;
}

#define CP16(dst, src) \
    asm volatile("cp.async.cg.shared.global [%0], [%1], 16;" :: "r"(dst), "l"(src) : "memory")
#define CP_COMMIT() asm volatile("cp.async.commit_group;" ::: "memory")
#define CP_WAIT(n)  asm volatile("cp.async.wait_group %0;" :: "n"(n) : "memory")

// ---------------------------------------------------------------------------
// Pre-pass A: g_xt = fp16(x) pairs, pair-perm'd.
// ---------------------------------------------------------------------------
__global__ __launch_bounds__(256) void xt_kernel(const float* __restrict__ x)
{
    int p = blockIdx.x * 256 + threadIdx.x;        // global pair index
    float2 v = ((const float2*)x)[p];
    g_xt[(p & ~15) | p16(p & 15)] = pack2(v.x, v.y);
}

// ---------------------------------------------------------------------------
// Pre-pass B: g_wt[mat][n][k-pairs] = fp16(W^T), pair-perm'd.
// ---------------------------------------------------------------------------
__global__ __launch_bounds__(256) void wt_kernel(
    const float* __restrict__ Wq, const float* __restrict__ Wk,
    const float* __restrict__ Wv)
{
    __shared__ float s[32][33];
    const float* W = (blockIdx.z == 0) ? Wq : (blockIdx.z == 1) ? Wk : Wv;
    const int k0 = blockIdx.x * 32, n0 = blockIdx.y * 32;
    const int tid = threadIdx.x;
    {
        int kl = tid >> 3, n4 = tid & 7;
        float4 v = *(const float4*)&W[(size_t)(k0 + kl) * CDIM + n0 + n4 * 4];
        s[kl][n4 * 4 + 0] = v.x; s[kl][n4 * 4 + 1] = v.y;
        s[kl][n4 * 4 + 2] = v.z; s[kl][n4 * 4 + 3] = v.w;
    }
    __syncthreads();
    {
        int nl = tid >> 3, k4 = tid & 7;
        unsigned uA = pack2(s[k4 * 4 + 0][nl], s[k4 * 4 + 1][nl]);
        unsigned uB = pack2(s[k4 * 4 + 2][nl], s[k4 * 4 + 3][nl]);
        size_t base = (size_t)(blockIdx.z * CDIM + n0 + nl) * 256;
        int pA = (k0 >> 1) + k4 * 2, pB = pA + 1;
        g_wt[base + ((pA & ~15) | p16(pA & 15))] = uA;
        g_wt[base + ((pB & ~15) | p16(pB & 15))] = uB;
    }
}

// ---------------------------------------------------------------------------
// Kernel 1: QKV projection, fp16 m16n8k16. CTA 128x128, 8 warps (2m x 4n).
// K=512 halves in 16 stages of 32, 4-deep cp.async pipeline, 2 CTAs/SM.
// (R11 version — proven best)
// ---------------------------------------------------------------------------
#define QKV_TILEA 2048                   // uints: 128 rows x 16
#define QKV_STAGE (2*QKV_TILEA)          // A + B = 4096 uints = 16KB
#define QKV_SMEMB (4*QKV_STAGE*4)        // 65536 bytes

__global__ __launch_bounds__(256, 2) void qkv_f16(
    const float* __restrict__ bq, const float* __restrict__ bk,
    const float* __restrict__ bv)
{
    extern __shared__ unsigned smem[];
    const uint32_t sbase = smem_u32(smem);

    const int tid  = threadIdx.x;
    const int lane = tid & 31;
    const int warp = tid >> 5;
    const int g    = lane >> 2;
    const int t    = lane & 3;
    const int wm   = (warp >> 2) * 64;
    const int wn   = (warp & 3) * 32;

    const int gx = blockIdx.x;           // 0..11
    const int gy = blockIdx.y;           // 0..255
    const bool isV = gx >= 8;
    const int mat  = isV ? 2 : (gx >> 2);
    const int col0 = isV ? 0 : (gx & 3) * 128;
    const int d0   = isV ? (gx - 8) * 128 : 0;
    const int r0   = gy * 128;

    const unsigned* Asrc;
    const unsigned* Bsrc;
    if (!isV) {
        Asrc = g_xt + (size_t)r0 * 256;
        Bsrc = g_wt + (size_t)(mat * CDIM + col0) * 256;
    } else {
        Asrc = g_wt + (size_t)(2 * CDIM + d0) * 256;
        Bsrc = g_xt + (size_t)r0 * 256;
    }
    const float* bias = (mat == 0) ? bq : (mat == 1) ? bk : bv;

    // staging: 4 CP16/thread/stage (A 512 chunks + B 512 chunks)
    const int srow = tid >> 1;           // 0..127
    const int sc   = tid & 1;
    const unsigned* aS = Asrc + (size_t)srow * 256 + sc * 8;
    const unsigned* bS = Bsrc + (size_t)srow * 256 + sc * 8;
    const uint32_t sOff = (uint32_t)(srow * 16 + sc * 8) * 4;

    auto stage = [&](int kt, int s) {
        uint32_t dA = sbase + (uint32_t)s * (QKV_STAGE * 4) + sOff;
        uint32_t dB = dA + QKV_TILEA * 4;
        const unsigned* sa = aS + kt * 16;
        const unsigned* sb = bS + kt * 16;
        CP16(dA, sa); CP16(dA + 16, sa + 4);
        CP16(dB, sb); CP16(dB + 16, sb + 4);
        CP_COMMIT();
    };

    float acc[4][4][4];
    #pragma unroll
    for (int mi = 0; mi < 4; mi++)
        #pragma unroll
        for (int ni = 0; ni < 4; ni++)
            #pragma unroll
            for (int e = 0; e < 4; e++) acc[mi][ni][e] = 0.f;

    stage(0, 0); stage(1, 1); stage(2, 2);

    for (int kt = 0; kt < 16; kt++) {
        CP_WAIT(2);
        __syncthreads();
        if (kt + 3 < 16) stage(kt + 3, (kt + 3) & 3);
        else             CP_COMMIT();

        const unsigned* As = smem + (kt & 3) * QKV_STAGE;
        const unsigned* Bs = As + QKV_TILEA;

        unsigned a0[4][4], a1[4][4];
        #pragma unroll
        for (int mi = 0; mi < 4; mi++) {
            int rb = wm + mi * 16 + g;
            uint4 lo = *(const uint4*)&As[rb * 16 + 4 * t];
            uint4 hi = *(const uint4*)&As[(rb + 8) * 16 + 4 * t];
            a0[mi][0] = lo.x; a0[mi][1] = hi.x; a0[mi][2] = lo.y; a0[mi][3] = hi.y;
            a1[mi][0] = lo.z; a1[mi][1] = hi.z; a1[mi][2] = lo.w; a1[mi][3] = hi.w;
        }
        #pragma unroll
        for (int ni = 0; ni < 4; ni++) {
            uint4 u = *(const uint4*)&Bs[(wn + ni * 8 + g) * 16 + 4 * t];
            unsigned b0[2] = { u.x, u.y }, b1[2] = { u.z, u.w };
            #pragma unroll
            for (int mi = 0; mi < 4; mi++) {
                mma_f16(acc[mi][ni], a0[mi], b0);
                mma_f16(acc[mi][ni], a1[mi], b1);
            }
        }
    }
    __syncthreads();

    // Epilogue
    const float kInv = 1.4426950408889634f * 0.125f;  // log2(e)/sqrt(64), folded into Q
    unsigned* qk = (mat == 0) ? g_q : g_k;

    #pragma unroll
    for (int mi = 0; mi < 4; mi++) {
        #pragma unroll
        for (int ep = 0; ep < 2; ep++) {
            int rowD = wm + mi * 16 + g + ep * 8;
            #pragma unroll
            for (int ni = 0; ni < 4; ni++) {
                float v0 = acc[mi][ni][2 * ep];
                float v1 = acc[mi][ni][2 * ep + 1];
                if (!isV) {
                    int R = r0 + rowD;
                    int bm = R >> 9, l = R & 511;
                    int c = col0 + wn + ni * 8 + t * 2;
                    int h = c >> 6, d = c & 63;
                    v0 += bias[c]; v1 += bias[c + 1];
                    if (mat == 0) { v0 *= kInv; v1 *= kInv; }
                    int dp = d >> 1;
                    int pos = (dp & ~15) | p16(dp & 15);
                    qk[((size_t)(bm * NH + h) * LSEQ + l) * 32 + pos] = pack2(v0, v1);
                } else {
                    int dg = d0 + rowD;              // 0..511
                    int h = dg >> 6, d = dg & 63;
                    int lc = wn + ni * 8 + t * 2;
                    int L = r0 + lc;
                    int bm = L >> 9, ll = L & 511;
                    float bv_ = bias[dg];
                    v0 += bv_; v1 += bv_;
                    int lp = ll >> 1;
                    int pos = (lp & ~15) | p16(lp & 15);
                    g_v[((size_t)(bm * NH + h) * HD + d) * 256 + pos] = pack2(v0, v1);
                }
            }
        }
    }
}

// ---------------------------------------------------------------------------
// Kernel 2: flash attention, fp16 m16n8k16. CTA 128 q-rows (8 warps x 16),
// 64-key j-tiles double-buffered, 2 CTAs/SM. Q frags via LDG.
// O^T = V^T P^T with P fragments SELF-OWNED (zero shuffles).
// ex2.approx.f16x2 halves MUFU work and directly yields packed P.
// lsum via ones-row MMA (racc) -> no rs reduction, in-lane normalizer.
// ---------------------------------------------------------------------------
#define AST 48
#define KS_OFF(b) ((b) * 64 * AST)
#define VS_OFF(b) (2 * 64 * AST + (b) * 64 * AST)
#define ATTN_SMEMB (4 * 64 * AST * 4)    // 49152 bytes

__global__ __launch_bounds__(256, 2) void attn_kernel(float* __restrict__ out)
{
    extern __shared__ unsigned asmem[];
    const uint32_t sbase = smem_u32(asmem);

    const int l0 = blockIdx.x * 128;
    const int h  = blockIdx.y;
    const int bm = blockIdx.z;

    const int tid  = threadIdx.x;
    const int lane = tid & 31;
    const int warp = tid >> 5;
    const int g    = lane >> 2;
    const int t    = lane & 3;
    const int wr   = warp * 16;

    const unsigned* qb = g_q + (size_t)(bm * NH + h) * LSEQ * 32;
    const unsigned* kb = g_k + (size_t)(bm * NH + h) * LSEQ * 32;
    const unsigned* vb = g_v + (size_t)(bm * NH + h) * HD * 256;

    const int sr = tid >> 2, sch = tid & 3;

    // ---- stage K0 + V0 ----
    {
        uint32_t dK = sbase + (uint32_t)(KS_OFF(0) + sr * AST + sch * 8) * 4;
        const unsigned* sK = kb + (size_t)sr * 32 + sch * 8;
        CP16(dK, sK); CP16(dK + 16, sK + 4);
        uint32_t dV = sbase + (uint32_t)(VS_OFF(0) + sr * AST + sch * 8) * 4;
        const unsigned* sV = vb + (size_t)sr * 256 + sch * 8;
        CP16(dV, sV); CP16(dV + 16, sV + 4);
        CP_COMMIT();
    }

    // ---- Q fragments via LDG (Q pre-scaled by log2(e)/8) ----
    unsigned qa[4][4];
    {
        const unsigned* p0 = qb + (size_t)(l0 + wr + g) * 32 + 4 * t;
        const unsigned* p8 = qb + (size_t)(l0 + wr + g + 8) * 32 + 4 * t;
        uint4 A0 = *(const uint4*)p0;
        uint4 A1 = *(const uint4*)(p0 + 16);
        uint4 B0 = *(const uint4*)p8;
        uint4 B1 = *(const uint4*)(p8 + 16);
        qa[0][0] = A0.x; qa[0][1] = B0.x; qa[0][2] = A0.y; qa[0][3] = B0.y;
        qa[1][0] = A0.z; qa[1][1] = B0.z; qa[1][2] = A0.w; qa[1][3] = B0.w;
        qa[2][0] = A1.x; qa[2][1] = B1.x; qa[2][2] = A1.y; qa[2][3] = B1.y;
        qa[3][0] = A1.z; qa[3][1] = B1.z; qa[3][2] = A1.w; qa[3][3] = B1.w;
    }

    float oacc[4][2][4];
    #pragma unroll
    for (int mi = 0; mi < 4; mi++)
        #pragma unroll
        for (int nq = 0; nq < 2; nq++)
            #pragma unroll
            for (int e = 0; e < 4; e++) oacc[mi][nq][e] = 0.f;

    float racc[2][4];                    // ones-row accumulators (row sums of P)
    #pragma unroll
    for (int e = 0; e < 2; e++)
        #pragma unroll
        for (int k = 0; k < 4; k++) racc[e][k] = 0.f;

    float mrow[2] = { -3.0e38f, -3.0e38f };

    CP_WAIT(0);
    __syncthreads();

    for (int j = 0; j < 8; j++) {
        const int b = j & 1;
        if (j < 7) {
            const int jn = (j + 1) * 64;
            uint32_t dK = sbase + (uint32_t)(KS_OFF(b ^ 1) + sr * AST + sch * 8) * 4;
            const unsigned* sK = kb + (size_t)(jn + sr) * 32 + sch * 8;
            CP16(dK, sK); CP16(dK + 16, sK + 4);
            uint32_t dV = sbase + (uint32_t)(VS_OFF(b ^ 1) + sr * AST + sch * 8) * 4;
            const unsigned* sV = vb + (size_t)sr * 256 + (jn >> 1) + sch * 8;
            CP16(dV, sV); CP16(dV + 16, sV + 4);
            CP_COMMIT();
        }

        const unsigned* Ks = asmem + KS_OFF(b);
        const unsigned* Vs = asmem + VS_OFF(b);

        // ---- S = Q K^T ----
        float sacc[8][4];
        #pragma unroll
        for (int ni = 0; ni < 8; ni++)
            #pragma unroll
            for (int e = 0; e < 4; e++) sacc[ni][e] = 0.f;

        #pragma unroll
        for (int ni = 0; ni < 8; ni++) {
            const unsigned* kr = Ks + (8 * ni + g) * AST + 4 * t;
            uint4 u0 = *(const uint4*)kr;
            uint4 u1 = *(const uint4*)(kr + 16);
            unsigned b0[2] = { u0.x, u0.y }, b1[2] = { u0.z, u0.w };
            unsigned b2[2] = { u1.x, u1.y }, b3[2] = { u1.z, u1.w };
            mma_f16(sacc[ni], qa[0], b0);
            mma_f16(sacc[ni], qa[1], b1);
            mma_f16(sacc[ni], qa[2], b2);
            mma_f16(sacc[ni], qa[3], b3);
        }

        // ---- per-half softmax + O-mma (f16x2 exp; lsum via ones-row mma) ---
        #pragma unroll
        for (int e = 0; e < 2; e++) {
            // max tree over 16 values
            float v8[8];
            #pragma unroll
            for (int ni = 0; ni < 8; ni++)
                v8[ni] = fmaxf(sacc[ni][2 * e], sacc[ni][2 * e + 1]);
            v8[0] = fmaxf(v8[0], v8[4]); v8[1] = fmaxf(v8[1], v8[5]);
            v8[2] = fmaxf(v8[2], v8[6]); v8[3] = fmaxf(v8[3], v8[7]);
            v8[0] = fmaxf(v8[0], v8[2]); v8[1] = fmaxf(v8[1], v8[3]);
            float mt = fmaxf(v8[0], v8[1]);
            mt = fmaxf(mt, __shfl_xor_sync(0xffffffffu, mt, 1));
            mt = fmaxf(mt, __shfl_xor_sync(0xffffffffu, mt, 2));
            float mnew = fmaxf(mrow[e], mt);
            float al = ex2(mrow[e] - mnew);
            mrow[e] = mnew;

            // P = exp2(S - mnew) as packed fp16 pairs (one MUFU per pair)
            unsigned ppl[8];
            #pragma unroll
            for (int ni = 0; ni < 8; ni++) {
                unsigned dd = pack2(sacc[ni][2 * e] - mnew,
                                    sacc[ni][2 * e + 1] - mnew);
                ppl[ni] = ex2_h2(dd);
            }

            // rescale this half's O^T columns + racc
            float a0 = __shfl_sync(0xffffffffu, al, 8 * t);
            float a1 = __shfl_sync(0xffffffffu, al, 8 * t + 4);
            #pragma unroll
            for (int mi = 0; mi < 4; mi++) {
                oacc[mi][e][0] *= a0; oacc[mi][e][2] *= a0;
                oacc[mi][e][1] *= a1; oacc[mi][e][3] *= a1;
            }
            racc[e][0] *= a0; racc[e][1] *= a1;
            racc[e][2] *= a0; racc[e][3] *= a1;

            // O^T += V^T P^T for this half (P frags self-owned)
            unsigned bb0[2] = { ppl[0], ppl[1] };
            unsigned bb1[2] = { ppl[2], ppl[3] };
            unsigned bb2[2] = { ppl[4], ppl[5] };
            unsigned bb3[2] = { ppl[6], ppl[7] };
            #pragma unroll
            for (int mi = 0; mi < 4; mi++) {
                const unsigned* vr  = Vs + (16 * mi + g) * AST + 4 * t;
                const unsigned* vr8 = Vs + (16 * mi + g + 8) * AST + 4 * t;
                uint4 lo = *(const uint4*)vr;
                uint4 hi = *(const uint4*)vr8;
                unsigned a0v[4] = { lo.x, hi.x, lo.y, hi.y };
                unsigned a1v[4] = { lo.z, hi.z, lo.w, hi.w };
                mma_f16(oacc[mi][e], a0v, bb0);
                mma_f16(oacc[mi][e], a1v, bb1);
                uint4 lo2 = *(const uint4*)(vr + 16);
                uint4 hi2 = *(const uint4*)(vr8 + 16);
                unsigned a2v[4] = { lo2.x, hi2.x, lo2.y, hi2.y };
                unsigned a3v[4] = { lo2.z, hi2.z, lo2.w, hi2.w };
                mma_f16(oacc[mi][e], a2v, bb2);
                mma_f16(oacc[mi][e], a3v, bb3);
            }
            // row sums of P via ones-row mma (lsum, alpha-consistent)
            {
                const unsigned one2 = 0x3C003C00u;
                unsigned aones[4] = { one2, one2, one2, one2 };
                mma_f16(racc[e], aones, bb0);
                mma_f16(racc[e], aones, bb1);
                mma_f16(racc[e], aones, bb2);
                mma_f16(racc[e], aones, bb3);
            }
        }

        if (j < 7) CP_WAIT(0);
        __syncthreads();
    }

    // ---- epilogue: in-lane normalizer (racc cols match oacc cols) ----
    #pragma unroll
    for (int nq = 0; nq < 2; nq++) {
        float inv0 = 1.f / racc[nq][0];
        float inv1 = 1.f / racc[nq][1];
        int q0 = l0 + wr + 8 * nq + 2 * t;
        float* o0 = out + ((size_t)bm * LSEQ + q0) * CDIM + h * HD;
        float* o1 = o0 + CDIM;
        #pragma unroll
        for (int mi = 0; mi < 4; mi++) {
            o0[mi * 16 + g]     = oacc[mi][nq][0] * inv0;
            o1[mi * 16 + g]     = oacc[mi][nq][1] * inv1;
            o0[mi * 16 + g + 8] = oacc[mi][nq][2] * inv0;
            o1[mi * 16 + g + 8] = oacc[mi][nq][3] * inv1;
        }
    }
}

extern "C" void kernel_launch(void* const* d_in, const int* in_sizes, int n_in,
                              void* d_out, int out_size)
{
    const float* x  = (const float*)d_in[0];
    const float* Wq = (const float*)d_in[1];
    const float* bq = (const float*)d_in[2];
    const float* Wk = (const float*)d_in[3];
    const float* bk = (const float*)d_in[4];
    const float* Wv = (const float*)d_in[5];
    const float* bv = (const float*)d_in[6];
    float* out = (float*)d_out;

    xt_kernel<<<NROWS * CDIM / 2 / 256, 256>>>(x);
    wt_kernel<<<dim3(16, 16, 3), 256>>>(Wq, Wk, Wv);

    cudaFuncSetAttribute(qkv_f16,
                         cudaFuncAttributeMaxDynamicSharedMemorySize, QKV_SMEMB);
    qkv_f16<<<dim3(12, 256), 256, QKV_SMEMB>>>(bq, bk, bv);

    cudaFuncSetAttribute(attn_kernel,
                         cudaFuncAttributeMaxDynamicSharedMemorySize, ATTN_SMEMB);
    attn_kernel<<<dim3(4, NH, NBM), 256, ATTN_SMEMB>>>(out);
}